// round 1
// baseline (speedup 1.0000x reference)
#include <cuda_runtime.h>

// Problem constants
#define T_  4
#define B_  4
#define C_  512
#define N_  1024          // H*W = 32*32
#define NH_ 8
#define HD_ 64
#define BCN  (B_*C_*N_)   // 2,097,152
#define TBCN (T_*BCN)     // 8,388,608
#define EPS_ 1e-5f

// ---------------------------------------------------------------------------
// Device scratch (static — no allocation anywhere)
// ---------------------------------------------------------------------------
__device__ float g_xs[TBCN];   // input spikes
__device__ float g_sq[TBCN];   // q spikes
__device__ float g_sk[TBCN];   // k spikes
__device__ float g_sv[TBCN];   // v spikes
__device__ float g_y [TBCN];   // pre-LIF scratch (reused 4x)
__device__ float g_os[TBCN];   // attention-output spikes
__device__ float g_kv[T_*B_*NH_*HD_*HD_];  // k^T v per (t,b,h): 128 x 64 x 64

__device__ __forceinline__ float* dev_buf(int sel) {
    switch (sel) {
        case 0: return g_xs;
        case 1: return g_sq;
        case 2: return g_sk;
        case 3: return g_sv;
        case 4: return g_y;
        case 5: return g_os;
        default: return g_y;
    }
}

// ---------------------------------------------------------------------------
// LIF scan over T (tau=2, hard reset to 0, heaviside spike: v >= vth)
// Layout [T, B, C, N]; each thread owns one (b,c,n) position.
// xsel < 0 -> read from external pointer Xext; else from dev_buf(xsel).
// ---------------------------------------------------------------------------
__global__ __launch_bounds__(256)
void lif_kernel(const float* __restrict__ Xext, int xsel, int ssel, float vth)
{
    int idx = blockIdx.x * blockDim.x + threadIdx.x;
    if (idx >= BCN) return;
    const float* X = (xsel < 0) ? Xext : dev_buf(xsel);
    float* S = dev_buf(ssel);

    float v = 0.f;
    #pragma unroll
    for (int t = 0; t < T_; t++) {
        float x = X[(size_t)t * BCN + idx];
        v = fmaf(x - v, 0.5f, v);            // v += (x - v)/tau, tau = 2
        float s = (v >= vth) ? 1.f : 0.f;
        S[(size_t)t * BCN + idx] = s;
        v = (v >= vth) ? 0.f : v;            // hard reset
    }
}

// ---------------------------------------------------------------------------
// Batched GEMM + (optional bias) + BatchNorm epilogue.
//   Y[batch, d, n] = ((sum_c W[d,c] * X[batch, c, n]) + bias[d] - mu[d]) * sc[d] + beta[d]
// batch = t*B + b (16 batches), M = C (d), N = N_, K = C.
// Tiling: BM=128, BN=64, BK=16; 256 threads; 8x4 per-thread microtile.
// ysel < 0 -> write to external Yext (final output); else dev_buf(ysel).
// ---------------------------------------------------------------------------
#define BM 128
#define BN 64
#define BK 16

__global__ __launch_bounds__(256)
void gemm_bn_kernel(int xsel,
                    const float* __restrict__ W,
                    const float* __restrict__ bias, int has_bias,
                    const float* __restrict__ gam, const float* __restrict__ bet,
                    const float* __restrict__ mu,  const float* __restrict__ var,
                    float* __restrict__ Yext, int ysel)
{
    const float* X = dev_buf(xsel);
    float* Y = (ysel < 0) ? Yext : dev_buf(ysel);

    int batch = blockIdx.z;
    int n0 = blockIdx.x * BN;
    int d0 = blockIdx.y * BM;
    const float* Xb = X + (size_t)batch * C_ * N_;
    float* Yb = Y + (size_t)batch * C_ * N_;

    __shared__ __align__(16) float Ws[BK][BM];   // [k][d]
    __shared__ __align__(16) float Xs[BK][BN];   // [k][n]

    int tid = threadIdx.x;
    int tx = tid & 15;    // n-group: n = n0 + tx*4 + j
    int ty = tid >> 4;    // d-group: d = d0 + ty*8 + i

    float acc[8][4];
    #pragma unroll
    for (int i = 0; i < 8; i++)
        #pragma unroll
        for (int j = 0; j < 4; j++) acc[i][j] = 0.f;

    for (int c0 = 0; c0 < C_; c0 += BK) {
        // Load W tile: 128x16 = 2048 elems, 8 per thread
        {
            int kl = tid & 15, dl = tid >> 4;
            #pragma unroll
            for (int r = 0; r < 8; r++)
                Ws[kl][dl + 16*r] = W[(size_t)(d0 + dl + 16*r) * C_ + (c0 + kl)];
        }
        // Load X tile: 16x64 = 1024 elems, 4 per thread (coalesced in n)
        {
            int nl = tid & 63, kl = tid >> 6;
            #pragma unroll
            for (int r = 0; r < 4; r++)
                Xs[kl + 4*r][nl] = Xb[(size_t)(c0 + kl + 4*r) * N_ + (n0 + nl)];
        }
        __syncthreads();

        #pragma unroll
        for (int kk = 0; kk < BK; kk++) {
            const float4* wr = (const float4*)Ws[kk];
            float4 a0 = wr[2*ty];
            float4 a1 = wr[2*ty + 1];
            float4 bq = ((const float4*)Xs[kk])[tx];
            float av[8] = {a0.x, a0.y, a0.z, a0.w, a1.x, a1.y, a1.z, a1.w};
            float bv[4] = {bq.x, bq.y, bq.z, bq.w};
            #pragma unroll
            for (int i = 0; i < 8; i++)
                #pragma unroll
                for (int j = 0; j < 4; j++)
                    acc[i][j] = fmaf(av[i], bv[j], acc[i][j]);
        }
        __syncthreads();
    }

    #pragma unroll
    for (int i = 0; i < 8; i++) {
        int d = d0 + ty*8 + i;
        float sc = gam[d] * rsqrtf(var[d] + EPS_);
        float sh = bet[d] - mu[d] * sc;
        float bs = has_bias ? bias[d] : 0.f;
        float4 o;
        o.x = (acc[i][0] + bs) * sc + sh;
        o.y = (acc[i][1] + bs) * sc + sh;
        o.z = (acc[i][2] + bs) * sc + sh;
        o.w = (acc[i][3] + bs) * sc + sh;
        ((float4*)(Yb + (size_t)d * N_ + n0))[tx] = o;
    }
}

// ---------------------------------------------------------------------------
// KV[e][dd] = sum_m k[t,b,h*64+e, m] * v[t,b,h*64+dd, m]   (per (t,b,h))
// One block per (t,b,h); 256 threads, 4x4 microtile, m tiled by 64.
// ---------------------------------------------------------------------------
__global__ __launch_bounds__(256)
void kv_kernel()
{
    int idx = blockIdx.x;          // 0..127 = (t*B+b)*8 + h
    int tb = idx >> 3, h = idx & 7;
    const float* Kb = g_sk + (size_t)tb * C_ * N_ + (size_t)h * HD_ * N_;
    const float* Vb = g_sv + (size_t)tb * C_ * N_ + (size_t)h * HD_ * N_;
    float* KVb = g_kv + (size_t)idx * HD_ * HD_;

    __shared__ float Ks[64][65];
    __shared__ float Vs[64][65];

    int tid = threadIdx.x;
    int tx = tid & 15;   // dd-group
    int ty = tid >> 4;   // e-group
    float acc[4][4];
    #pragma unroll
    for (int i = 0; i < 4; i++)
        #pragma unroll
        for (int j = 0; j < 4; j++) acc[i][j] = 0.f;

    for (int m0 = 0; m0 < N_; m0 += 64) {
        int mm = tid & 63, e0 = tid >> 6;   // 4 rows per pass
        #pragma unroll
        for (int r = 0; r < 16; r++) {
            Ks[e0 + 4*r][mm] = Kb[(size_t)(e0 + 4*r) * N_ + m0 + mm];
            Vs[e0 + 4*r][mm] = Vb[(size_t)(e0 + 4*r) * N_ + m0 + mm];
        }
        __syncthreads();
        #pragma unroll 8
        for (int mm2 = 0; mm2 < 64; mm2++) {
            float a[4], b[4];
            #pragma unroll
            for (int i = 0; i < 4; i++) a[i] = Ks[ty*4 + i][mm2];
            #pragma unroll
            for (int j = 0; j < 4; j++) b[j] = Vs[tx*4 + j][mm2];
            #pragma unroll
            for (int i = 0; i < 4; i++)
                #pragma unroll
                for (int j = 0; j < 4; j++)
                    acc[i][j] = fmaf(a[i], b[j], acc[i][j]);
        }
        __syncthreads();
    }
    #pragma unroll
    for (int i = 0; i < 4; i++)
        #pragma unroll
        for (int j = 0; j < 4; j++)
            KVb[(size_t)(ty*4 + i) * HD_ + (tx*4 + j)] = acc[i][j];
}

// ---------------------------------------------------------------------------
// o_pre[t,b,h*64+dd, n] = 0.125 * sum_e q[t,b,h*64+e, n] * KV[e][dd]
// grid.x: n tiles of 128; grid.y: (t,b,h). One n per thread, all 64 dd.
// ---------------------------------------------------------------------------
__global__ __launch_bounds__(128)
void qkv_apply_kernel()
{
    int idx = blockIdx.y;
    int tb = idx >> 3, h = idx & 7;
    int n = blockIdx.x * 128 + threadIdx.x;
    const float* Qb  = g_sq + (size_t)tb * C_ * N_ + (size_t)h * HD_ * N_;
    const float* KVb = g_kv + (size_t)idx * HD_ * HD_;
    float* Ob = g_y + (size_t)tb * C_ * N_ + (size_t)h * HD_ * N_;

    __shared__ __align__(16) float KVs[HD_ * HD_];
    for (int i = threadIdx.x; i < HD_ * HD_; i += 128) KVs[i] = KVb[i];
    __syncthreads();

    float acc[64];
    #pragma unroll
    for (int d = 0; d < 64; d++) acc[d] = 0.f;

    for (int e = 0; e < 64; e++) {
        float qv = Qb[(size_t)e * N_ + n];
        const float4* row = (const float4*)(KVs + e * 64);
        #pragma unroll
        for (int dq = 0; dq < 16; dq++) {
            float4 kvv = row[dq];
            acc[dq*4+0] = fmaf(qv, kvv.x, acc[dq*4+0]);
            acc[dq*4+1] = fmaf(qv, kvv.y, acc[dq*4+1]);
            acc[dq*4+2] = fmaf(qv, kvv.z, acc[dq*4+2]);
            acc[dq*4+3] = fmaf(qv, kvv.w, acc[dq*4+3]);
        }
    }
    #pragma unroll
    for (int d = 0; d < 64; d++)
        Ob[(size_t)d * N_ + n] = acc[d] * 0.125f;
}

// ---------------------------------------------------------------------------
// Launch
// ---------------------------------------------------------------------------
extern "C" void kernel_launch(void* const* d_in, const int* in_sizes, int n_in,
                              void* d_out, int out_size)
{
    const float* x   = (const float*)d_in[0];
    const float* Wq  = (const float*)d_in[1];
    const float* q_g = (const float*)d_in[2];
    const float* q_b = (const float*)d_in[3];
    const float* q_m = (const float*)d_in[4];
    const float* q_v = (const float*)d_in[5];
    const float* Wk  = (const float*)d_in[6];
    const float* k_g = (const float*)d_in[7];
    const float* k_b = (const float*)d_in[8];
    const float* k_m = (const float*)d_in[9];
    const float* k_v = (const float*)d_in[10];
    const float* Wv  = (const float*)d_in[11];
    const float* v_g = (const float*)d_in[12];
    const float* v_b = (const float*)d_in[13];
    const float* v_m = (const float*)d_in[14];
    const float* v_v = (const float*)d_in[15];
    const float* Wp  = (const float*)d_in[16];
    const float* bp  = (const float*)d_in[17];
    const float* p_g = (const float*)d_in[18];
    const float* p_b = (const float*)d_in[19];
    const float* p_m = (const float*)d_in[20];
    const float* p_v = (const float*)d_in[21];
    float* out = (float*)d_out;

    const int LIF_BLOCKS = BCN / 256;
    dim3 gemm_grid(N_ / BN, C_ / BM, T_ * B_);

    // 1) Input LIF -> spikes in g_xs (buf 0)
    lif_kernel<<<LIF_BLOCKS, 256>>>(x, -1, 0, 1.0f);

    // 2) Q/K/V: GEMM + BN -> g_y (4), then LIF -> g_sq/g_sk/g_sv (1/2/3)
    gemm_bn_kernel<<<gemm_grid, 256>>>(0, Wq, nullptr, 0, q_g, q_b, q_m, q_v, nullptr, 4);
    lif_kernel<<<LIF_BLOCKS, 256>>>(nullptr, 4, 1, 1.0f);

    gemm_bn_kernel<<<gemm_grid, 256>>>(0, Wk, nullptr, 0, k_g, k_b, k_m, k_v, nullptr, 4);
    lif_kernel<<<LIF_BLOCKS, 256>>>(nullptr, 4, 2, 1.0f);

    gemm_bn_kernel<<<gemm_grid, 256>>>(0, Wv, nullptr, 0, v_g, v_b, v_m, v_v, nullptr, 4);
    lif_kernel<<<LIF_BLOCKS, 256>>>(nullptr, 4, 3, 1.0f);

    // 3) Attention via exact re-association: KV = k^T v (64x64 per t,b,h)
    kv_kernel<<<T_ * B_ * NH_, 256>>>();

    // 4) o_pre = 0.125 * q @ KV -> g_y, then attn LIF (vth=0.5) -> g_os (5)
    qkv_apply_kernel<<<dim3(N_ / 128, T_ * B_ * NH_), 128>>>();
    lif_kernel<<<LIF_BLOCKS, 256>>>(nullptr, 4, 5, 0.5f);

    // 5) Projection: GEMM + bias + BN -> d_out
    gemm_bn_kernel<<<gemm_grid, 256>>>(5, Wp, bp, 1, p_g, p_b, p_m, p_v, out, -1);
}